// round 2
// baseline (speedup 1.0000x reference)
#include <cuda_runtime.h>

// GatingNetwork: B=4096 tokens, D=1024 (x = concat(t1,t2) -> 2048), E=64 experts.
// logits[b,e] = -sqrt(||w_e - x_b||^2); top-2 softmax scattered into (B,E).
//
// Decomposition: S = ||x||^2 + (||w_e||^2 - 2 w_e.x). Ordering uses only the
// per-expert part p_e = wsq[e] - 2*dot (error ~1e-6), ||x||^2 added back only
// for the sqrt/softmax values (common term, ordering-irrelevant).

#define B_TOK   4096
#define D_HALF  1024
#define KDIM    2048
#define NEXP    64
#define KC      128     // K-chunk staged in smem
#define WS_PITCH 132    // 128 + 4 pad: conflict-managed LDS.128, 16B-aligned rows
#define TPW     2       // tokens per warp

__device__ float g_xsq[B_TOK];
__device__ float g_wsq[NEXP];

// ---------------------------------------------------------------------------
// Kernel 1: row norms. blocks [0,4096) -> ||x_b||^2, [4096,4160) -> ||w_e||^2
// ---------------------------------------------------------------------------
__global__ void norms_kernel(const float* __restrict__ t1,
                             const float* __restrict__ t2,
                             const float* __restrict__ w) {
    int row = blockIdx.x;
    int tid = threadIdx.x;          // 128 threads
    float s = 0.f;
    if (row < B_TOK) {
        const float4* a = (const float4*)(t1 + (size_t)row * D_HALF);
        const float4* b = (const float4*)(t2 + (size_t)row * D_HALF);
        for (int i = tid; i < D_HALF / 4; i += 128) {
            float4 v = a[i]; s += v.x*v.x + v.y*v.y + v.z*v.z + v.w*v.w;
            float4 u = b[i]; s += u.x*u.x + u.y*u.y + u.z*u.z + u.w*u.w;
        }
    } else {
        const float4* a = (const float4*)(w + (size_t)(row - B_TOK) * KDIM);
        for (int i = tid; i < KDIM / 4; i += 128) {
            float4 v = a[i]; s += v.x*v.x + v.y*v.y + v.z*v.z + v.w*v.w;
        }
    }
    __shared__ float red[128];
    red[tid] = s;
    __syncthreads();
    for (int off = 64; off > 0; off >>= 1) {
        if (tid < off) red[tid] += red[tid + off];
        __syncthreads();
    }
    if (tid == 0) {
        if (row < B_TOK) g_xsq[row] = red[0];
        else             g_wsq[row - B_TOK] = red[0];
    }
}

// ordering predicate: smaller S first; jax.lax.top_k tie-break = lower index
__device__ __forceinline__ bool sless(float a, int ia, float b, int ib) {
    return (a < b) || (a == b && ia < ib);
}

// ---------------------------------------------------------------------------
// Kernel 2: main. CTA = 256 thr (8 warps), warp owns TPW tokens,
// lane owns experts (lane, lane+32). W staged in smem per K-chunk.
// ---------------------------------------------------------------------------
__global__ __launch_bounds__(256) void gate_kernel(const float* __restrict__ t1,
                                                   const float* __restrict__ t2,
                                                   const float* __restrict__ w,
                                                   float* __restrict__ out) {
    __shared__ float ws[NEXP * WS_PITCH];   // 33 KB

    const int tid  = threadIdx.x;
    const int lane = tid & 31;
    const int wid  = tid >> 5;
    const int tokBase = blockIdx.x * (8 * TPW) + wid * TPW;

    const int e0 = lane;
    const int e1 = lane + 32;

    float acc[TPW][2];
#pragma unroll
    for (int t = 0; t < TPW; t++) { acc[t][0] = 0.f; acc[t][1] = 0.f; }

    // smem fill mapping: thread -> (expert e = tid/4, quarter q = tid%4),
    // 8 float4 per thread, 64B-contiguous global chunks per j.
    const int fe = tid >> 2;
    const int fq = tid & 3;

    for (int k0 = 0; k0 < KDIM; k0 += KC) {
        __syncthreads();   // protect previous chunk's readers
        {
            const float4* src = (const float4*)(w + (size_t)fe * KDIM + k0);
            float4* dst = (float4*)(ws + fe * WS_PITCH);
#pragma unroll
            for (int j = 0; j < 8; j++) {
                dst[fq + j * 4] = src[fq + j * 4];
            }
        }
        __syncthreads();

        const float4* xp[TPW];
#pragma unroll
        for (int t = 0; t < TPW; t++) {
            const float* base = (k0 < D_HALF)
                ? (t1 + (size_t)(tokBase + t) * D_HALF + k0)
                : (t2 + (size_t)(tokBase + t) * D_HALF + (k0 - D_HALF));
            xp[t] = (const float4*)base;
        }
        const float4* w0 = (const float4*)(ws + e0 * WS_PITCH);
        const float4* w1 = (const float4*)(ws + e1 * WS_PITCH);

#pragma unroll 8
        for (int kk = 0; kk < KC / 4; kk++) {
            float4 wa = w0[kk];
            float4 wb = w1[kk];
#pragma unroll
            for (int t = 0; t < TPW; t++) {
                float4 xv = xp[t][kk];
                float a0 = acc[t][0];
                a0 = fmaf(wa.x, xv.x, a0);
                a0 = fmaf(wa.y, xv.y, a0);
                a0 = fmaf(wa.z, xv.z, a0);
                a0 = fmaf(wa.w, xv.w, a0);
                acc[t][0] = a0;
                float a1 = acc[t][1];
                a1 = fmaf(wb.x, xv.x, a1);
                a1 = fmaf(wb.y, xv.y, a1);
                a1 = fmaf(wb.z, xv.z, a1);
                a1 = fmaf(wb.w, xv.w, a1);
                acc[t][1] = a1;
            }
        }
    }

    // ----- epilogue: per-token top-2 (smallest S) + softmax + scatter -----
    const float wsq0 = g_wsq[e0];
    const float wsq1 = g_wsq[e1];

#pragma unroll
    for (int t = 0; t < TPW; t++) {
        const int tok = tokBase + t;
        float p0 = wsq0 - 2.f * acc[t][0];
        float p1 = wsq1 - 2.f * acc[t][1];

        float v1, v2; int i1, i2;
        if (sless(p0, e0, p1, e1)) { v1 = p0; i1 = e0; v2 = p1; i2 = e1; }
        else                        { v1 = p1; i1 = e1; v2 = p0; i2 = e0; }

#pragma unroll
        for (int off = 16; off > 0; off >>= 1) {
            float u1 = __shfl_xor_sync(0xffffffffu, v1, off);
            int   j1 = __shfl_xor_sync(0xffffffffu, i1, off);
            float u2 = __shfl_xor_sync(0xffffffffu, v2, off);
            int   j2 = __shfl_xor_sync(0xffffffffu, i2, off);
            float n1, n2; int m1, m2;
            if (sless(u1, j1, v1, i1)) {
                n1 = u1; m1 = j1;
                if (sless(v1, i1, u2, j2)) { n2 = v1; m2 = i1; }
                else                        { n2 = u2; m2 = j2; }
            } else {
                n1 = v1; m1 = i1;
                if (sless(u1, j1, v2, i2)) { n2 = u1; m2 = j1; }
                else                        { n2 = v2; m2 = i2; }
            }
            v1 = n1; i1 = m1; v2 = n2; i2 = m2;
        }

        const float xsq = g_xsq[tok];
        const float l1 = -__fsqrt_rn(xsq + v1);   // best logit
        const float l2 = -__fsqrt_rn(xsq + v2);   // second logit
        const float ed = expf(l2 - l1);           // <= 1
        const float inv = 1.f / (1.f + ed);
        const float gw1 = inv;
        const float gw2 = ed * inv;

        float o0 = (e0 == i1) ? gw1 : ((e0 == i2) ? gw2 : 0.f);
        float o1 = (e1 == i1) ? gw1 : ((e1 == i2) ? gw2 : 0.f);
        out[(size_t)tok * NEXP + e0] = o0;
        out[(size_t)tok * NEXP + e1] = o1;
    }
}

// ---------------------------------------------------------------------------
extern "C" void kernel_launch(void* const* d_in, const int* in_sizes, int n_in,
                              void* d_out, int out_size) {
    const float* t1 = (const float*)d_in[0];
    const float* t2 = (const float*)d_in[1];
    const float* w  = (const float*)d_in[2];
    float* out = (float*)d_out;

    norms_kernel<<<B_TOK + NEXP, 128>>>(t1, t2, w);
    gate_kernel<<<B_TOK / (8 * TPW), 256>>>(t1, t2, w, out);
}

// round 4
// speedup vs baseline: 1.5745x; 1.5745x over previous
#include <cuda_runtime.h>
#include <cstdint>

// GatingNetwork: B=4096, x = concat(t1,t2) -> K=2048, E=64 experts.
// logits[b,e] = -sqrt(||w_e - x_b||^2); top-2 softmax scattered into (B,E).
// Ordering key: p_e = ||w_e||^2 - 2 w_e.x  (||x||^2 common, added back for values).
//
// gate_kernel: register-blocked GEMM. CTA=128thr, tile 32 tok x 64 exp,
// thread tile 4x4, KC=128 K-chunks double-buffered via cp.async.

#define B_TOK   4096
#define D_HALF  1024
#define KDIM    2048
#define NEXP    64
#define KC      128
#define NCHUNK  (KDIM / KC)          // 16
#define PITCH   132                  // floats per smem row (33 float4, odd -> conflict-free)
#define P4      (PITCH / 4)          // 33
#define TM      32                   // tokens per CTA
#define NTHR    128
#define WOFF    (TM * PITCH)         // float offset of W region in a buffer
#define BUFF    ((TM + NEXP) * PITCH)// floats per buffer = 12672
#define SMEM_BYTES (2 * BUFF * 4)    // 101376 bytes

__device__ float g_wsq[NEXP];

// ---------------------------------------------------------------------------
__global__ void wsq_kernel(const float* __restrict__ w) {
    int e = blockIdx.x;
    const float4* row = (const float4*)(w + (size_t)e * KDIM);
    float s = 0.f;
    for (int i = threadIdx.x; i < KDIM / 4; i += 256) {
        float4 v = row[i];
        s += v.x * v.x + v.y * v.y + v.z * v.z + v.w * v.w;
    }
#pragma unroll
    for (int o = 16; o; o >>= 1) s += __shfl_xor_sync(0xffffffffu, s, o);
    __shared__ float red[8];
    if ((threadIdx.x & 31) == 0) red[threadIdx.x >> 5] = s;
    __syncthreads();
    if (threadIdx.x == 0) {
        float t = 0.f;
#pragma unroll
        for (int i = 0; i < 8; i++) t += red[i];
        g_wsq[e] = t;
    }
}

// ---------------------------------------------------------------------------
__device__ __forceinline__ void cp16(uint32_t dst, const void* src) {
    asm volatile("cp.async.cg.shared.global [%0], [%1], 16;" :: "r"(dst), "l"(src));
}
__device__ __forceinline__ void cp_commit() {
    asm volatile("cp.async.commit_group;");
}
template <int N>
__device__ __forceinline__ void cp_wait() {
    asm volatile("cp.async.wait_group %0;" :: "n"(N));
}

__device__ __forceinline__ bool sless(float a, int ia, float b, int ib) {
    return (a < b) || (a == b && ia < ib);
}

// ---------------------------------------------------------------------------
__global__ __launch_bounds__(NTHR) void gate_kernel(const float* __restrict__ t1,
                                                    const float* __restrict__ t2,
                                                    const float* __restrict__ w,
                                                    float* __restrict__ out) {
    extern __shared__ float sm[];
    const int tid  = threadIdx.x;
    const int lane = tid & 31;
    const int tx   = tid & 15;        // expert group: experts {tx + 16j}
    const int ty   = tid >> 4;        // token group: tokens 4ty..4ty+3
    const int tokBase = blockIdx.x * TM;
    const int myTok = tx & 3;         // which of the 4 tokens this lane tracks ||x||^2 for

    const uint32_t sbase = (uint32_t)__cvta_generic_to_shared(sm);

    float acc[4][4];                  // [token][expert j]
#pragma unroll
    for (int t = 0; t < 4; t++)
#pragma unroll
        for (int j = 0; j < 4; j++) acc[t][j] = 0.f;
    float4 xacc = make_float4(0.f, 0.f, 0.f, 0.f);

    // ---- stage chunk into buffer via cp.async (16B ops, L1 bypass) ----
    auto stage = [&](int chunk, int buf) {
        const int k0 = chunk * KC;
        const uint32_t bufb = sbase + (uint32_t)buf * (BUFF * 4);
        const float* xsrc = (k0 < D_HALF) ? t1 : t2;
        const int kx = k0 & (D_HALF - 1);
#pragma unroll
        for (int r = 0; r < 8; r++) {                 // 1024 float4 of X
            int i = tid + NTHR * r;
            int row = i >> 5, c = i & 31;
            cp16(bufb + (uint32_t)(row * PITCH + c * 4) * 4,
                 xsrc + (size_t)(tokBase + row) * D_HALF + kx + c * 4);
        }
#pragma unroll
        for (int r = 0; r < 16; r++) {                // 2048 float4 of W
            int i = tid + NTHR * r;
            int row = i >> 5, c = i & 31;
            cp16(bufb + (uint32_t)(WOFF + row * PITCH + c * 4) * 4,
                 w + (size_t)row * KDIM + k0 + c * 4);
        }
    };

    stage(0, 0);
    cp_commit();

    for (int chunk = 0; chunk < NCHUNK; chunk++) {
        const int buf = chunk & 1;
        if (chunk + 1 < NCHUNK) {
            stage(chunk + 1, buf ^ 1);
            cp_commit();
            cp_wait<1>();
        } else {
            cp_wait<0>();
        }
        __syncthreads();

        const float* sbuf = sm + buf * BUFF;
        const float4* xr0 = (const float4*)(sbuf + (4 * ty + 0) * PITCH);
        const float4* xr1 = (const float4*)(sbuf + (4 * ty + 1) * PITCH);
        const float4* xr2 = (const float4*)(sbuf + (4 * ty + 2) * PITCH);
        const float4* xr3 = (const float4*)(sbuf + (4 * ty + 3) * PITCH);
        const float4* wr  = (const float4*)(sbuf + WOFF + tx * PITCH);

#pragma unroll 8
        for (int kk = 0; kk < KC / 4; kk++) {
            float4 xv0 = xr0[kk];
            float4 xv1 = xr1[kk];
            float4 xv2 = xr2[kk];
            float4 xv3 = xr3[kk];

            // ||x||^2 for this lane's assigned token (SEL chain, alu pipe)
            float4 mx = (myTok & 2) ? ((myTok & 1) ? xv3 : xv2)
                                    : ((myTok & 1) ? xv1 : xv0);
            xacc.x = fmaf(mx.x, mx.x, xacc.x);
            xacc.y = fmaf(mx.y, mx.y, xacc.y);
            xacc.z = fmaf(mx.z, mx.z, xacc.z);
            xacc.w = fmaf(mx.w, mx.w, xacc.w);

#pragma unroll
            for (int j = 0; j < 4; j++) {
                float4 wv = wr[kk + j * (16 * P4)];
                acc[0][j] = fmaf(wv.x, xv0.x, acc[0][j]);
                acc[0][j] = fmaf(wv.y, xv0.y, acc[0][j]);
                acc[0][j] = fmaf(wv.z, xv0.z, acc[0][j]);
                acc[0][j] = fmaf(wv.w, xv0.w, acc[0][j]);
                acc[1][j] = fmaf(wv.x, xv1.x, acc[1][j]);
                acc[1][j] = fmaf(wv.y, xv1.y, acc[1][j]);
                acc[1][j] = fmaf(wv.z, xv1.z, acc[1][j]);
                acc[1][j] = fmaf(wv.w, xv1.w, acc[1][j]);
                acc[2][j] = fmaf(wv.x, xv2.x, acc[2][j]);
                acc[2][j] = fmaf(wv.y, xv2.y, acc[2][j]);
                acc[2][j] = fmaf(wv.z, xv2.z, acc[2][j]);
                acc[2][j] = fmaf(wv.w, xv2.w, acc[2][j]);
                acc[3][j] = fmaf(wv.x, xv3.x, acc[3][j]);
                acc[3][j] = fmaf(wv.y, xv3.y, acc[3][j]);
                acc[3][j] = fmaf(wv.z, xv3.z, acc[3][j]);
                acc[3][j] = fmaf(wv.w, xv3.w, acc[3][j]);
            }
        }
        __syncthreads();
    }

    // ---- epilogue ----
    // share per-token ||x||^2 within each 4-lane subgroup
    const float xs_own = xacc.x + xacc.y + xacc.z + xacc.w;
    float xs_all[4];
#pragma unroll
    for (int i = 0; i < 4; i++)
        xs_all[i] = __shfl_sync(0xffffffffu, xs_own, (lane & ~3) | i);

    float wsqv[4];
#pragma unroll
    for (int j = 0; j < 4; j++) wsqv[j] = g_wsq[tx + 16 * j];

#pragma unroll
    for (int t = 0; t < 4; t++) {
        const int tok = tokBase + 4 * ty + t;

        float v1 = 1e30f, v2 = 1e30f;
        int   i1 = 1 << 20, i2 = 1 << 20;
#pragma unroll
        for (int j = 0; j < 4; j++) {
            float p = fmaf(-2.f, acc[t][j], wsqv[j]);
            int e = tx + 16 * j;
            if (sless(p, e, v1, i1)) { v2 = v1; i2 = i1; v1 = p; i1 = e; }
            else if (sless(p, e, v2, i2)) { v2 = p; i2 = e; }
        }
        // merge across the 16 lanes holding this token's experts
#pragma unroll
        for (int off = 1; off <= 8; off <<= 1) {
            float u1 = __shfl_xor_sync(0xffffffffu, v1, off);
            int   j1 = __shfl_xor_sync(0xffffffffu, i1, off);
            float u2 = __shfl_xor_sync(0xffffffffu, v2, off);
            int   j2 = __shfl_xor_sync(0xffffffffu, i2, off);
            float n1, n2; int m1, m2;
            if (sless(u1, j1, v1, i1)) {
                n1 = u1; m1 = j1;
                if (sless(v1, i1, u2, j2)) { n2 = v1; m2 = i1; }
                else                        { n2 = u2; m2 = j2; }
            } else {
                n1 = v1; m1 = i1;
                if (sless(u1, j1, v2, i2)) { n2 = u1; m2 = j1; }
                else                        { n2 = v2; m2 = i2; }
            }
            v1 = n1; i1 = m1; v2 = n2; i2 = m2;
        }

        float xq = xs_all[t];
        float s1 = xq + v1; s1 = s1 > 0.f ? s1 : 0.f;
        float s2 = xq + v2; s2 = s2 > 0.f ? s2 : 0.f;
        const float l1 = -__fsqrt_rn(s1);
        const float l2 = -__fsqrt_rn(s2);
        const float ed = __expf(l2 - l1);          // <= 1
        const float inv = 1.f / (1.f + ed);
        const float g1 = inv;
        const float g2 = ed * inv;

#pragma unroll
        for (int j = 0; j < 4; j++) {
            int e = tx + 16 * j;
            float o = (e == i1) ? g1 : ((e == i2) ? g2 : 0.f);
            out[(size_t)tok * NEXP + e] = o;
        }
    }
}

// ---------------------------------------------------------------------------
extern "C" void kernel_launch(void* const* d_in, const int* in_sizes, int n_in,
                              void* d_out, int out_size) {
    const float* t1 = (const float*)d_in[0];
    const float* t2 = (const float*)d_in[1];
    const float* w  = (const float*)d_in[2];
    float* out = (float*)d_out;

    cudaFuncSetAttribute(gate_kernel,
                         cudaFuncAttributeMaxDynamicSharedMemorySize, SMEM_BYTES);

    wsq_kernel<<<NEXP, 256>>>(w);
    gate_kernel<<<B_TOK / TM, NTHR, SMEM_BYTES>>>(t1, t2, w, out);
}

// round 6
// speedup vs baseline: 2.4045x; 1.5272x over previous
#include <cuda_runtime.h>
#include <cstdint>

// GatingNetwork: B=4096 tokens, x=concat(t1,t2) -> K=2048, E=64 experts.
// logits[b,e] = -sqrt(||w_e - x_b||^2); top-2 softmax scattered into (B,E).
//
// Round 5: warp-level mma.sync bf16-split GEMM (portable PTX; tcgen05 is
// rejected because the harness targets plain sm_103).
// dot = xh*wh + xh*wl + xl*wh accumulated in fp32; exact fp32 ||x||^2, ||w||^2.

#define B_TOK   4096
#define D_HALF  1024
#define KDIM    2048
#define NEXP    64
#define TILE_M  32
#define KC      64
#define NCHUNK  (KDIM / KC)       // 32
#define NTHR    256

// smem (bytes): double-buffered chunk staging, bf16 rows padded to 144B
#define RPITCH  144               // 64 bf16 = 128B data + 16B pad (LDSM conflict-free)
#define XH_OFF  0
#define XL_OFF  (TILE_M * RPITCH)             // 4608
#define WH_OFF  (2 * TILE_M * RPITCH)         // 9216
#define WL_OFF  (2 * TILE_M * RPITCH + NEXP * RPITCH)  // 18432
#define BUF_B   (2 * TILE_M * RPITCH + 2 * NEXP * RPITCH)  // 27648
#define SMEM_TOTAL (2 * BUF_B)    // 55296
#define DP      68                // dots pitch (floats)

__device__ uint32_t g_wh[NEXP * KDIM / 2];   // bf16x2 packed
__device__ uint32_t g_wl[NEXP * KDIM / 2];
__device__ float    g_wsq[NEXP];

// ---------------------------------------------------------------------------
__device__ __forceinline__ uint32_t smem_u32(const void* p) {
    uint32_t a;
    asm("{ .reg .u64 t; cvta.to.shared.u64 t, %1; cvt.u32.u64 %0, t; }"
        : "=r"(a) : "l"(p));
    return a;
}
__device__ __forceinline__ void cp16(uint32_t dst, const void* src) {
    asm volatile("cp.async.cg.shared.global [%0], [%1], 16;" :: "r"(dst), "l"(src));
}
__device__ __forceinline__ void cp_commit() { asm volatile("cp.async.commit_group;"); }
template <int N>
__device__ __forceinline__ void cp_wait() {
    asm volatile("cp.async.wait_group %0;" :: "n"(N));
}
// pack two f32 -> bf16x2 (first arg in low half)
__device__ __forceinline__ uint32_t pack_bf2(float lo, float hi) {
    uint32_t d;
    asm("cvt.rn.bf16x2.f32 %0, %1, %2;" : "=r"(d) : "f"(hi), "f"(lo));
    return d;
}
__device__ __forceinline__ void sts128(uint32_t a, uint32_t v0, uint32_t v1,
                                       uint32_t v2, uint32_t v3) {
    asm volatile("st.shared.v4.b32 [%0], {%1,%2,%3,%4};"
                 :: "r"(a), "r"(v0), "r"(v1), "r"(v2), "r"(v3) : "memory");
}

#define LDSM4(r, addr) \
    asm volatile("ldmatrix.sync.aligned.m8n8.x4.shared.b16 {%0,%1,%2,%3}, [%4];" \
        : "=r"((r)[0]), "=r"((r)[1]), "=r"((r)[2]), "=r"((r)[3]) : "r"(addr))

#define MMA(c, a, b0_, b1_) \
    asm volatile("mma.sync.aligned.m16n8k16.row.col.f32.bf16.bf16.f32 " \
        "{%0,%1,%2,%3}, {%4,%5,%6,%7}, {%8,%9}, {%0,%1,%2,%3};" \
        : "+f"((c)[0]), "+f"((c)[1]), "+f"((c)[2]), "+f"((c)[3]) \
        : "r"((a)[0]), "r"((a)[1]), "r"((a)[2]), "r"((a)[3]), "r"(b0_), "r"(b1_))

__device__ __forceinline__ bool sless(float a, int ia, float b, int ib) {
    return (a < b) || (a == b && ia < ib);
}

// ---------------------------------------------------------------------------
// Kernel 1: split W into bf16 hi/lo, exact ||w||^2.
// ---------------------------------------------------------------------------
__global__ __launch_bounds__(256) void wsplit_kernel(const float* __restrict__ w) {
    const int row = blockIdx.x;
    const int t = threadIdx.x;
    const float4* src = (const float4*)(w + (size_t)row * KDIM);
    float q = 0.f;
    for (int i = t; i < KDIM / 4; i += 256) {
        float4 v = src[i];
        uint32_t h0 = pack_bf2(v.x, v.y);
        uint32_t h1 = pack_bf2(v.z, v.w);
        float r0 = v.x - __uint_as_float(h0 << 16);
        float r1 = v.y - __uint_as_float(h0 & 0xffff0000u);
        float r2 = v.z - __uint_as_float(h1 << 16);
        float r3 = v.w - __uint_as_float(h1 & 0xffff0000u);
        uint32_t l0 = pack_bf2(r0, r1);
        uint32_t l1 = pack_bf2(r2, r3);
        q = fmaf(v.x, v.x, q); q = fmaf(v.y, v.y, q);
        q = fmaf(v.z, v.z, q); q = fmaf(v.w, v.w, q);
        g_wh[row * (KDIM / 2) + 2 * i]     = h0;
        g_wh[row * (KDIM / 2) + 2 * i + 1] = h1;
        g_wl[row * (KDIM / 2) + 2 * i]     = l0;
        g_wl[row * (KDIM / 2) + 2 * i + 1] = l1;
    }
#pragma unroll
    for (int o = 16; o; o >>= 1) q += __shfl_xor_sync(0xffffffffu, q, o);
    __shared__ float red[8];
    if ((t & 31) == 0) red[t >> 5] = q;
    __syncthreads();
    if (t == 0) {
        float s = 0.f;
#pragma unroll
        for (int i = 0; i < 8; i++) s += red[i];
        g_wsq[row] = s;
    }
}

// ---------------------------------------------------------------------------
// Kernel 2: fused GEMM + top-2 + softmax + scatter.
// CTA = 32 tokens x 64 experts x K=2048.  8 warps, warp tile 16m x 16n.
// ---------------------------------------------------------------------------
__global__ __launch_bounds__(NTHR) void gemm_kernel(const float* __restrict__ t1,
                                                    const float* __restrict__ t2,
                                                    float* __restrict__ out) {
    extern __shared__ char smem[];
    const uint32_t sb = smem_u32(smem);
    const int tid  = threadIdx.x;
    const int lane = tid & 31;
    const int wid  = tid >> 5;
    const int wm   = wid & 1;       // m16 half
    const int wn   = wid >> 1;      // n16 quarter
    const int tokBase = blockIdx.x * TILE_M;

    // LDSM lane address offsets (within a tile, bytes)
    const uint32_t aoff = (uint32_t)((wm * 16 + (lane & 15)) * RPITCH + (lane >> 4) * 16);
    const uint32_t boff = (uint32_t)((wn * 16 + ((lane & 7) | ((lane >> 4) << 3))) * RPITCH
                                     + ((lane >> 3) & 1) * 16);

    // X staging mapping: thread -> (row, 8-float segment)
    const int xr = tid >> 3;        // 0..31
    const int xs = tid & 7;         // 0..7

    float acc0[4] = {0.f, 0.f, 0.f, 0.f};   // n-tile 0
    float acc1[4] = {0.f, 0.f, 0.f, 0.f};   // n-tile 1
    float xq = 0.f;                          // exact ||x||^2 partial (row xr)

    auto stage = [&](int chunk, int buf) {
        const int k0 = chunk * KC;
        const uint32_t bufb = sb + (uint32_t)buf * BUF_B;
        // ---- W hi/lo via cp.async: 1024 x 16B, 4 per thread ----
#pragma unroll
        for (int j = 0; j < 4; j++) {
            int i = tid + NTHR * j;           // 0..1023
            int half = i >> 9;                // 0: hi, 1: lo
            int r = (i >> 3) & 63;
            int c = i & 7;
            const uint32_t* srcb = half ? g_wl : g_wh;
            cp16(bufb + (half ? WL_OFF : WH_OFF) + (uint32_t)(r * RPITCH + c * 16),
                 srcb + ((size_t)r * (KDIM / 2) + (k0 >> 1) + c * 4));
        }
        cp_commit();
        // ---- X: load fp32, split, STS ----
        const float* xsrc = (k0 < D_HALF) ? t1 : t2;
        const int kx = k0 & (D_HALF - 1);
        const float4* xp = (const float4*)(xsrc + (size_t)(tokBase + xr) * D_HALF + kx + xs * 8);
        float4 v0 = xp[0];
        float4 v1 = xp[1];
        uint32_t h0 = pack_bf2(v0.x, v0.y);
        uint32_t h1 = pack_bf2(v0.z, v0.w);
        uint32_t h2 = pack_bf2(v1.x, v1.y);
        uint32_t h3 = pack_bf2(v1.z, v1.w);
        uint32_t l0 = pack_bf2(v0.x - __uint_as_float(h0 << 16),
                               v0.y - __uint_as_float(h0 & 0xffff0000u));
        uint32_t l1 = pack_bf2(v0.z - __uint_as_float(h1 << 16),
                               v0.w - __uint_as_float(h1 & 0xffff0000u));
        uint32_t l2 = pack_bf2(v1.x - __uint_as_float(h2 << 16),
                               v1.y - __uint_as_float(h2 & 0xffff0000u));
        uint32_t l3 = pack_bf2(v1.z - __uint_as_float(h3 << 16),
                               v1.w - __uint_as_float(h3 & 0xffff0000u));
        xq = fmaf(v0.x, v0.x, xq); xq = fmaf(v0.y, v0.y, xq);
        xq = fmaf(v0.z, v0.z, xq); xq = fmaf(v0.w, v0.w, xq);
        xq = fmaf(v1.x, v1.x, xq); xq = fmaf(v1.y, v1.y, xq);
        xq = fmaf(v1.z, v1.z, xq); xq = fmaf(v1.w, v1.w, xq);
        uint32_t xa = (uint32_t)(xr * RPITCH + xs * 16);
        sts128(bufb + XH_OFF + xa, h0, h1, h2, h3);
        sts128(bufb + XL_OFF + xa, l0, l1, l2, l3);
    };

    stage(0, 0);

    for (int c = 0; c < NCHUNK; c++) {
        cp_wait<0>();
        __syncthreads();
        if (c + 1 < NCHUNK) stage(c + 1, (c + 1) & 1);

        const uint32_t bufb = sb + (uint32_t)(c & 1) * BUF_B;
#pragma unroll
        for (int ks = 0; ks < 4; ks++) {
            uint32_t ah[4], al[4], bh[4], bl[4];
            LDSM4(ah, bufb + XH_OFF + aoff + ks * 32);
            LDSM4(bh, bufb + WH_OFF + boff + ks * 32);
            LDSM4(al, bufb + XL_OFF + aoff + ks * 32);
            LDSM4(bl, bufb + WL_OFF + boff + ks * 32);
            MMA(acc0, ah, bh[0], bh[1]);
            MMA(acc1, ah, bh[2], bh[3]);
            MMA(acc0, al, bh[0], bh[1]);
            MMA(acc1, al, bh[2], bh[3]);
            MMA(acc0, ah, bl[0], bl[1]);
            MMA(acc1, ah, bl[2], bl[3]);
        }
        __syncthreads();
    }

    // ---- epilogue: dots -> smem, top-2, softmax, scatter ----
    float* dots = (float*)smem;              // [32][DP]
    float* sxq  = dots + TILE_M * DP;        // [32]

    {
        int r0 = wm * 16 + (lane >> 2);
        int cc = wn * 16 + (lane & 3) * 2;
        dots[r0 * DP + cc]           = acc0[0];
        dots[r0 * DP + cc + 1]       = acc0[1];
        dots[(r0 + 8) * DP + cc]     = acc0[2];
        dots[(r0 + 8) * DP + cc + 1] = acc0[3];
        dots[r0 * DP + cc + 8]       = acc1[0];
        dots[r0 * DP + cc + 9]       = acc1[1];
        dots[(r0 + 8) * DP + cc + 8] = acc1[2];
        dots[(r0 + 8) * DP + cc + 9] = acc1[3];
    }
    // reduce ||x||^2 over the 8 segment-threads of each row (same warp)
#pragma unroll
    for (int o = 4; o; o >>= 1) xq += __shfl_xor_sync(0xffffffffu, xq, o);
    if ((tid & 7) == 0) sxq[xr] = xq;
    __syncthreads();

    const float w0 = g_wsq[lane];
    const float w1 = g_wsq[lane + 32];
    const int e0 = lane, e1 = lane + 32;

#pragma unroll
    for (int tt = 0; tt < 4; tt++) {
        const int rloc = wid * 4 + tt;
        const int tok = tokBase + rloc;
        float d0 = dots[rloc * DP + e0];
        float d1 = dots[rloc * DP + e1];
        float p0 = fmaf(-2.f, d0, w0);
        float p1 = fmaf(-2.f, d1, w1);

        float v1, v2; int i1, i2;
        if (sless(p0, e0, p1, e1)) { v1 = p0; i1 = e0; v2 = p1; i2 = e1; }
        else                        { v1 = p1; i1 = e1; v2 = p0; i2 = e0; }
#pragma unroll
        for (int off = 16; off > 0; off >>= 1) {
            float u1 = __shfl_xor_sync(0xffffffffu, v1, off);
            int   j1 = __shfl_xor_sync(0xffffffffu, i1, off);
            float u2 = __shfl_xor_sync(0xffffffffu, v2, off);
            int   j2 = __shfl_xor_sync(0xffffffffu, i2, off);
            float n1, n2; int m1, m2;
            if (sless(u1, j1, v1, i1)) {
                n1 = u1; m1 = j1;
                if (sless(v1, i1, u2, j2)) { n2 = v1; m2 = i1; }
                else                        { n2 = u2; m2 = j2; }
            } else {
                n1 = v1; m1 = i1;
                if (sless(u1, j1, v2, i2)) { n2 = u1; m2 = j1; }
                else                        { n2 = v2; m2 = i2; }
            }
            v1 = n1; i1 = m1; v2 = n2; i2 = m2;
        }

        const float xqv = sxq[rloc];
        float s1 = xqv + v1; s1 = s1 > 0.f ? s1 : 0.f;
        float s2 = xqv + v2; s2 = s2 > 0.f ? s2 : 0.f;
        const float lg1 = -__fsqrt_rn(s1);
        const float lg2 = -__fsqrt_rn(s2);
        const float ed  = __expf(lg2 - lg1);     // <= 1
        const float inv = 1.f / (1.f + ed);
        const float ga  = inv;
        const float gb  = ed * inv;

        float o0 = (e0 == i1) ? ga : ((e0 == i2) ? gb : 0.f);
        float o1 = (e1 == i1) ? ga : ((e1 == i2) ? gb : 0.f);
        out[(size_t)tok * NEXP + e0] = o0;
        out[(size_t)tok * NEXP + e1] = o1;
    }
}

// ---------------------------------------------------------------------------
extern "C" void kernel_launch(void* const* d_in, const int* in_sizes, int n_in,
                              void* d_out, int out_size) {
    const float* t1 = (const float*)d_in[0];
    const float* t2 = (const float*)d_in[1];
    const float* w  = (const float*)d_in[2];
    float* out = (float*)d_out;

    cudaFuncSetAttribute(gemm_kernel,
                         cudaFuncAttributeMaxDynamicSharedMemorySize, SMEM_TOTAL);

    wsplit_kernel<<<NEXP, 256>>>(w);
    gemm_kernel<<<B_TOK / TILE_M, NTHR, SMEM_TOTAL>>>(t1, t2, out);
}

// round 7
// speedup vs baseline: 2.8325x; 1.1780x over previous
#include <cuda_runtime.h>
#include <cstdint>

// GatingNetwork: B=4096 tokens, x=concat(t1,t2) -> K=2048, E=64 experts.
// logits[b,e] = -sqrt(||w_e - x_b||^2); top-2 softmax scattered into (B,E).
//
// Round 6: mma.sync bf16-split GEMM with a real software pipeline:
//   - W: 4-stage cp.async, issued 3 chunks ahead (latency fully hidden)
//   - X: LDG register-prefetch one chunk ahead, convert+STS double-buffered
//   - one __syncthreads per chunk
// dot = xh*wh + xh*wl + xl*wh in fp32 accum; exact fp32 ||x||^2 / ||w||^2.

#define B_TOK   4096
#define D_HALF  1024
#define KDIM    2048
#define NEXP    64
#define TILE_M  32
#define KC      64
#define NCHUNK  (KDIM / KC)       // 32
#define NTHR    256
#define WSTAGES 4

#define RPITCH  144               // 64 bf16 = 128B + 16B pad (LDSM conflict-free)
// X buffer: 2 stages x (hi+lo) x 32 rows
#define XSTG_B  (2 * TILE_M * RPITCH)         // 9216
#define XH_OFF  0
#define XL_OFF  (TILE_M * RPITCH)             // 4608
// W buffer: 4 stages x (hi+lo) x 64 rows
#define WSTG_B  (2 * NEXP * RPITCH)           // 18432
#define WH_OFF  0
#define WL_OFF  (NEXP * RPITCH)               // 9216
#define WBASE   (2 * XSTG_B)                  // 18432
#define SMEM_TOTAL (WBASE + WSTAGES * WSTG_B) // 92160
#define DP      68                // dots pitch (floats)

__device__ uint32_t g_wh[NEXP * KDIM / 2];   // bf16x2 packed
__device__ uint32_t g_wl[NEXP * KDIM / 2];
__device__ float    g_wsq[NEXP];

// ---------------------------------------------------------------------------
__device__ __forceinline__ uint32_t smem_u32(const void* p) {
    uint32_t a;
    asm("{ .reg .u64 t; cvta.to.shared.u64 t, %1; cvt.u32.u64 %0, t; }"
        : "=r"(a) : "l"(p));
    return a;
}
__device__ __forceinline__ void cp16(uint32_t dst, const void* src) {
    asm volatile("cp.async.cg.shared.global [%0], [%1], 16;" :: "r"(dst), "l"(src));
}
__device__ __forceinline__ void cp_commit() { asm volatile("cp.async.commit_group;"); }
template <int N>
__device__ __forceinline__ void cp_wait() {
    asm volatile("cp.async.wait_group %0;" :: "n"(N));
}
__device__ __forceinline__ uint32_t pack_bf2(float lo, float hi) {
    uint32_t d;
    asm("cvt.rn.bf16x2.f32 %0, %1, %2;" : "=r"(d) : "f"(hi), "f"(lo));
    return d;
}
__device__ __forceinline__ void sts128(uint32_t a, uint32_t v0, uint32_t v1,
                                       uint32_t v2, uint32_t v3) {
    asm volatile("st.shared.v4.b32 [%0], {%1,%2,%3,%4};"
                 :: "r"(a), "r"(v0), "r"(v1), "r"(v2), "r"(v3) : "memory");
}

#define LDSM4(r, addr) \
    asm volatile("ldmatrix.sync.aligned.m8n8.x4.shared.b16 {%0,%1,%2,%3}, [%4];" \
        : "=r"((r)[0]), "=r"((r)[1]), "=r"((r)[2]), "=r"((r)[3]) : "r"(addr))

#define MMA(c, a, b0_, b1_) \
    asm volatile("mma.sync.aligned.m16n8k16.row.col.f32.bf16.bf16.f32 " \
        "{%0,%1,%2,%3}, {%4,%5,%6,%7}, {%8,%9}, {%0,%1,%2,%3};" \
        : "+f"((c)[0]), "+f"((c)[1]), "+f"((c)[2]), "+f"((c)[3]) \
        : "r"((a)[0]), "r"((a)[1]), "r"((a)[2]), "r"((a)[3]), "r"(b0_), "r"(b1_))

__device__ __forceinline__ bool sless(float a, int ia, float b, int ib) {
    return (a < b) || (a == b && ia < ib);
}

// ---------------------------------------------------------------------------
// Kernel 1: split W into bf16 hi/lo, exact ||w||^2.
// ---------------------------------------------------------------------------
__global__ __launch_bounds__(256) void wsplit_kernel(const float* __restrict__ w) {
    const int row = blockIdx.x;
    const int t = threadIdx.x;
    const float4* src = (const float4*)(w + (size_t)row * KDIM);
    float q = 0.f;
    for (int i = t; i < KDIM / 4; i += 256) {
        float4 v = src[i];
        uint32_t h0 = pack_bf2(v.x, v.y);
        uint32_t h1 = pack_bf2(v.z, v.w);
        float r0 = v.x - __uint_as_float(h0 << 16);
        float r1 = v.y - __uint_as_float(h0 & 0xffff0000u);
        float r2 = v.z - __uint_as_float(h1 << 16);
        float r3 = v.w - __uint_as_float(h1 & 0xffff0000u);
        uint32_t l0 = pack_bf2(r0, r1);
        uint32_t l1 = pack_bf2(r2, r3);
        q = fmaf(v.x, v.x, q); q = fmaf(v.y, v.y, q);
        q = fmaf(v.z, v.z, q); q = fmaf(v.w, v.w, q);
        g_wh[row * (KDIM / 2) + 2 * i]     = h0;
        g_wh[row * (KDIM / 2) + 2 * i + 1] = h1;
        g_wl[row * (KDIM / 2) + 2 * i]     = l0;
        g_wl[row * (KDIM / 2) + 2 * i + 1] = l1;
    }
#pragma unroll
    for (int o = 16; o; o >>= 1) q += __shfl_xor_sync(0xffffffffu, q, o);
    __shared__ float red[8];
    if ((t & 31) == 0) red[t >> 5] = q;
    __syncthreads();
    if (t == 0) {
        float s = 0.f;
#pragma unroll
        for (int i = 0; i < 8; i++) s += red[i];
        g_wsq[row] = s;
    }
}

// ---------------------------------------------------------------------------
// Kernel 2: fused GEMM + top-2 + softmax + scatter.
// CTA = 32 tokens x 64 experts x K=2048. 8 warps, warp tile m16 x n16.
// ---------------------------------------------------------------------------
__global__ __launch_bounds__(NTHR) void gemm_kernel(const float* __restrict__ t1,
                                                    const float* __restrict__ t2,
                                                    float* __restrict__ out) {
    extern __shared__ char smem[];
    const uint32_t sb = smem_u32(smem);
    const int tid  = threadIdx.x;
    const int lane = tid & 31;
    const int wid  = tid >> 5;
    const int wm   = wid & 1;       // m16 half
    const int wn   = wid >> 1;      // n16 quarter
    const int tokBase = blockIdx.x * TILE_M;

    const uint32_t aoff = (uint32_t)((wm * 16 + (lane & 15)) * RPITCH + (lane >> 4) * 16);
    const uint32_t boff = (uint32_t)((wn * 16 + ((lane & 7) | ((lane >> 4) << 3))) * RPITCH
                                     + ((lane >> 3) & 1) * 16);

    const int xr = tid >> 3;        // X staging row 0..31
    const int xs = tid & 7;         // 8-float segment

    float acc0[4] = {0.f, 0.f, 0.f, 0.f};
    float acc1[4] = {0.f, 0.f, 0.f, 0.f};
    float xq = 0.f;
    float4 rx0, rx1;                // register-prefetched X for next chunk

    auto ldgX = [&](int chunk) {
        const int k0 = chunk * KC;
        const float* xsrc = (k0 < D_HALF) ? t1 : t2;
        const int kx = k0 & (D_HALF - 1);
        const float4* xp = (const float4*)(xsrc + (size_t)(tokBase + xr) * D_HALF + kx + xs * 8);
        rx0 = xp[0];
        rx1 = xp[1];
    };
    auto stsX = [&](int buf) {
        uint32_t h0 = pack_bf2(rx0.x, rx0.y);
        uint32_t h1 = pack_bf2(rx0.z, rx0.w);
        uint32_t h2 = pack_bf2(rx1.x, rx1.y);
        uint32_t h3 = pack_bf2(rx1.z, rx1.w);
        uint32_t l0 = pack_bf2(rx0.x - __uint_as_float(h0 << 16),
                               rx0.y - __uint_as_float(h0 & 0xffff0000u));
        uint32_t l1 = pack_bf2(rx0.z - __uint_as_float(h1 << 16),
                               rx0.w - __uint_as_float(h1 & 0xffff0000u));
        uint32_t l2 = pack_bf2(rx1.x - __uint_as_float(h2 << 16),
                               rx1.y - __uint_as_float(h2 & 0xffff0000u));
        uint32_t l3 = pack_bf2(rx1.z - __uint_as_float(h3 << 16),
                               rx1.w - __uint_as_float(h3 & 0xffff0000u));
        xq = fmaf(rx0.x, rx0.x, xq); xq = fmaf(rx0.y, rx0.y, xq);
        xq = fmaf(rx0.z, rx0.z, xq); xq = fmaf(rx0.w, rx0.w, xq);
        xq = fmaf(rx1.x, rx1.x, xq); xq = fmaf(rx1.y, rx1.y, xq);
        xq = fmaf(rx1.z, rx1.z, xq); xq = fmaf(rx1.w, rx1.w, xq);
        uint32_t xb = sb + (uint32_t)buf * XSTG_B + (uint32_t)(xr * RPITCH + xs * 16);
        sts128(xb + XH_OFF, h0, h1, h2, h3);
        sts128(xb + XL_OFF, l0, l1, l2, l3);
    };
    auto cpW = [&](int chunk) {
        const int k0 = chunk * KC;
        const uint32_t wb = sb + WBASE + (uint32_t)(chunk & (WSTAGES - 1)) * WSTG_B;
#pragma unroll
        for (int j = 0; j < 4; j++) {
            int i = tid + NTHR * j;           // 0..1023
            int half = i >> 9;                // 0: hi, 1: lo
            int r = (i >> 3) & 63;
            int c = i & 7;
            const uint32_t* srcb = half ? g_wl : g_wh;
            cp16(wb + (half ? WL_OFF : WH_OFF) + (uint32_t)(r * RPITCH + c * 16),
                 srcb + ((size_t)r * (KDIM / 2) + (k0 >> 1) + c * 4));
        }
        cp_commit();
    };

    // prologue: X regs for chunk 0, W stages 0..2 in flight
    ldgX(0);
    cpW(0); cpW(1); cpW(2);

    for (int c = 0; c < NCHUNK; c++) {
        stsX(c & 1);                           // chunk c into X buffer
        if (c + 1 < NCHUNK) ldgX(c + 1);       // overlap DRAM latency with compute
        cp_wait<2>();                          // W_c landed (c+1, c+2 still in flight)
        __syncthreads();                       // X_c + W_c visible; c-1 compute done
        if (c + 3 < NCHUNK) cpW(c + 3);        // targets wbuf[(c-1)%4], readers done

        const uint32_t xb = sb + (uint32_t)(c & 1) * XSTG_B;
        const uint32_t wb = sb + WBASE + (uint32_t)(c & (WSTAGES - 1)) * WSTG_B;
#pragma unroll
        for (int ks = 0; ks < 4; ks++) {
            uint32_t ah[4], al[4], bh[4], bl[4];
            LDSM4(ah, xb + XH_OFF + aoff + ks * 32);
            LDSM4(bh, wb + WH_OFF + boff + ks * 32);
            LDSM4(al, xb + XL_OFF + aoff + ks * 32);
            LDSM4(bl, wb + WL_OFF + boff + ks * 32);
            MMA(acc0, ah, bh[0], bh[1]);
            MMA(acc1, ah, bh[2], bh[3]);
            MMA(acc0, al, bh[0], bh[1]);
            MMA(acc1, al, bh[2], bh[3]);
            MMA(acc0, ah, bl[0], bl[1]);
            MMA(acc1, ah, bl[2], bl[3]);
        }
    }
    __syncthreads();                           // all compute done before smem reuse

    // ---- epilogue: dots -> smem, top-2, softmax, scatter ----
    float* dots = (float*)smem;                // [32][DP]
    float* sxq  = dots + TILE_M * DP;          // [32]

    {
        int r0 = wm * 16 + (lane >> 2);
        int cc = wn * 16 + (lane & 3) * 2;
        dots[r0 * DP + cc]           = acc0[0];
        dots[r0 * DP + cc + 1]       = acc0[1];
        dots[(r0 + 8) * DP + cc]     = acc0[2];
        dots[(r0 + 8) * DP + cc + 1] = acc0[3];
        dots[r0 * DP + cc + 8]       = acc1[0];
        dots[r0 * DP + cc + 9]       = acc1[1];
        dots[(r0 + 8) * DP + cc + 8] = acc1[2];
        dots[(r0 + 8) * DP + cc + 9] = acc1[3];
    }
#pragma unroll
    for (int o = 4; o; o >>= 1) xq += __shfl_xor_sync(0xffffffffu, xq, o);
    if ((tid & 7) == 0) sxq[xr] = xq;
    __syncthreads();

    const float w0 = g_wsq[lane];
    const float w1 = g_wsq[lane + 32];
    const int e0 = lane, e1 = lane + 32;

#pragma unroll
    for (int tt = 0; tt < 4; tt++) {
        const int rloc = wid * 4 + tt;
        const int tok = tokBase + rloc;
        float d0 = dots[rloc * DP + e0];
        float d1 = dots[rloc * DP + e1];
        float p0 = fmaf(-2.f, d0, w0);
        float p1 = fmaf(-2.f, d1, w1);

        float v1, v2; int i1, i2;
        if (sless(p0, e0, p1, e1)) { v1 = p0; i1 = e0; v2 = p1; i2 = e1; }
        else                        { v1 = p1; i1 = e1; v2 = p0; i2 = e0; }
#pragma unroll
        for (int off = 16; off > 0; off >>= 1) {
            float u1 = __shfl_xor_sync(0xffffffffu, v1, off);
            int   j1 = __shfl_xor_sync(0xffffffffu, i1, off);
            float u2 = __shfl_xor_sync(0xffffffffu, v2, off);
            int   j2 = __shfl_xor_sync(0xffffffffu, i2, off);
            float n1, n2; int m1, m2;
            if (sless(u1, j1, v1, i1)) {
                n1 = u1; m1 = j1;
                if (sless(v1, i1, u2, j2)) { n2 = v1; m2 = i1; }
                else                        { n2 = u2; m2 = j2; }
            } else {
                n1 = v1; m1 = i1;
                if (sless(u1, j1, v2, i2)) { n2 = u1; m2 = j1; }
                else                        { n2 = v2; m2 = i2; }
            }
            v1 = n1; i1 = m1; v2 = n2; i2 = m2;
        }

        const float xqv = sxq[rloc];
        float s1 = xqv + v1; s1 = s1 > 0.f ? s1 : 0.f;
        float s2 = xqv + v2; s2 = s2 > 0.f ? s2 : 0.f;
        const float lg1 = -__fsqrt_rn(s1);
        const float lg2 = -__fsqrt_rn(s2);
        const float ed  = __expf(lg2 - lg1);
        const float inv = 1.f / (1.f + ed);
        const float ga  = inv;
        const float gb  = ed * inv;

        float o0 = (e0 == i1) ? ga : ((e0 == i2) ? gb : 0.f);
        float o1 = (e1 == i1) ? ga : ((e1 == i2) ? gb : 0.f);
        out[(size_t)tok * NEXP + e0] = o0;
        out[(size_t)tok * NEXP + e1] = o1;
    }
}

// ---------------------------------------------------------------------------
extern "C" void kernel_launch(void* const* d_in, const int* in_sizes, int n_in,
                              void* d_out, int out_size) {
    const float* t1 = (const float*)d_in[0];
    const float* t2 = (const float*)d_in[1];
    const float* w  = (const float*)d_in[2];
    float* out = (float*)d_out;

    cudaFuncSetAttribute(gemm_kernel,
                         cudaFuncAttributeMaxDynamicSharedMemorySize, SMEM_TOTAL);

    wsplit_kernel<<<NEXP, 256>>>(w);
    gemm_kernel<<<B_TOK / TILE_M, NTHR, SMEM_TOTAL>>>(t1, t2, out);
}

// round 9
// speedup vs baseline: 3.4620x; 1.2222x over previous
#include <cuda_runtime.h>
#include <cstdint>

// GatingNetwork: B=4096 tokens, x=concat(t1,t2) -> K=2048, E=64 experts.
// logits[b,e] = -sqrt(||w_e - x_b||^2); top-2 softmax scattered into (B,E).
//
// Round 7: mma.sync bf16-split GEMM, 512 threads / 16 warps.
// Warp = (m16 half) x (n32 half) x (k16 slice of each 64-wide chunk):
// 4 warps per SMSP hide LDSM/MMA latency. K-split partials merged in smem.
// dot = xh*wh + xh*wl + xl*wh in fp32; exact fp32 ||x||^2 / ||w||^2.

#define B_TOK   4096
#define D_HALF  1024
#define KDIM    2048
#define NEXP    64
#define TILE_M  32
#define KC      64
#define NCHUNK  (KDIM / KC)       // 32
#define NTHR    512
#define WSTAGES 4

#define RPITCH  144               // 64 bf16 = 128B + 16B pad (LDSM conflict-free)
#define XSTG_B  (2 * TILE_M * RPITCH)         // 9216 (hi+lo, 32 rows)
#define XH_OFF  0
#define XL_OFF  (TILE_M * RPITCH)             // 4608
#define WSTG_B  (2 * NEXP * RPITCH)           // 18432
#define WH_OFF  0
#define WL_OFF  (NEXP * RPITCH)               // 9216
#define WBASE   (2 * XSTG_B)                  // 18432
#define SMEM_TOTAL (WBASE + WSTAGES * WSTG_B) // 92160
#define DP      68                // dots pitch (floats)

__device__ uint32_t g_wh[NEXP * KDIM / 2];   // bf16x2 packed
__device__ uint32_t g_wl[NEXP * KDIM / 2];
__device__ float    g_wsq[NEXP];

// ---------------------------------------------------------------------------
__device__ __forceinline__ uint32_t smem_u32(const void* p) {
    uint32_t a;
    asm("{ .reg .u64 t; cvta.to.shared.u64 t, %1; cvt.u32.u64 %0, t; }"
        : "=r"(a) : "l"(p));
    return a;
}
__device__ __forceinline__ void cp16(uint32_t dst, const void* src) {
    asm volatile("cp.async.cg.shared.global [%0], [%1], 16;" :: "r"(dst), "l"(src));
}
__device__ __forceinline__ void cp_commit() { asm volatile("cp.async.commit_group;"); }
template <int N>
__device__ __forceinline__ void cp_wait() {
    asm volatile("cp.async.wait_group %0;" :: "n"(N));
}
__device__ __forceinline__ uint32_t pack_bf2(float lo, float hi) {
    uint32_t d;
    asm("cvt.rn.bf16x2.f32 %0, %1, %2;" : "=r"(d) : "f"(hi), "f"(lo));
    return d;
}
__device__ __forceinline__ void sts64(uint32_t a, uint32_t v0, uint32_t v1) {
    asm volatile("st.shared.v2.b32 [%0], {%1,%2};"
                 :: "r"(a), "r"(v0), "r"(v1) : "memory");
}

#define LDSM4(r, addr) \
    asm volatile("ldmatrix.sync.aligned.m8n8.x4.shared.b16 {%0,%1,%2,%3}, [%4];" \
        : "=r"((r)[0]), "=r"((r)[1]), "=r"((r)[2]), "=r"((r)[3]) : "r"(addr))

#define MMA(c, a, b0_, b1_) \
    asm volatile("mma.sync.aligned.m16n8k16.row.col.f32.bf16.bf16.f32 " \
        "{%0,%1,%2,%3}, {%4,%5,%6,%7}, {%8,%9}, {%0,%1,%2,%3};" \
        : "+f"((c)[0]), "+f"((c)[1]), "+f"((c)[2]), "+f"((c)[3]) \
        : "r"((a)[0]), "r"((a)[1]), "r"((a)[2]), "r"((a)[3]), "r"(b0_), "r"(b1_))

__device__ __forceinline__ bool sless(float a, int ia, float b, int ib) {
    return (a < b) || (a == b && ia < ib);
}

// ---------------------------------------------------------------------------
// Kernel 1: split W into bf16 hi/lo, exact ||w||^2.
// ---------------------------------------------------------------------------
__global__ __launch_bounds__(256) void wsplit_kernel(const float* __restrict__ w) {
    const int row = blockIdx.x;
    const int t = threadIdx.x;
    const float4* src = (const float4*)(w + (size_t)row * KDIM);
    float q = 0.f;
    for (int i = t; i < KDIM / 4; i += 256) {
        float4 v = src[i];
        uint32_t h0 = pack_bf2(v.x, v.y);
        uint32_t h1 = pack_bf2(v.z, v.w);
        float r0 = v.x - __uint_as_float(h0 << 16);
        float r1 = v.y - __uint_as_float(h0 & 0xffff0000u);
        float r2 = v.z - __uint_as_float(h1 << 16);
        float r3 = v.w - __uint_as_float(h1 & 0xffff0000u);
        uint32_t l0 = pack_bf2(r0, r1);
        uint32_t l1 = pack_bf2(r2, r3);
        q = fmaf(v.x, v.x, q); q = fmaf(v.y, v.y, q);
        q = fmaf(v.z, v.z, q); q = fmaf(v.w, v.w, q);
        g_wh[row * (KDIM / 2) + 2 * i]     = h0;
        g_wh[row * (KDIM / 2) + 2 * i + 1] = h1;
        g_wl[row * (KDIM / 2) + 2 * i]     = l0;
        g_wl[row * (KDIM / 2) + 2 * i + 1] = l1;
    }
#pragma unroll
    for (int o = 16; o; o >>= 1) q += __shfl_xor_sync(0xffffffffu, q, o);
    __shared__ float red[8];
    if ((t & 31) == 0) red[t >> 5] = q;
    __syncthreads();
    if (t == 0) {
        float s = 0.f;
#pragma unroll
        for (int i = 0; i < 8; i++) s += red[i];
        g_wsq[row] = s;
    }
}

// ---------------------------------------------------------------------------
// Kernel 2: fused GEMM + top-2 + softmax + scatter.
// CTA = 32 tokens x 64 experts x K=2048. 16 warps: (wm, wn2, wk).
// ---------------------------------------------------------------------------
__global__ __launch_bounds__(NTHR) void gemm_kernel(const float* __restrict__ t1,
                                                    const float* __restrict__ t2,
                                                    float* __restrict__ out) {
    extern __shared__ char smem[];
    const uint32_t sb = smem_u32(smem);
    const int tid  = threadIdx.x;
    const int lane = tid & 31;
    const int wid  = tid >> 5;
    const int wk   = wid & 3;        // k16 slice within a chunk
    const int wn2  = (wid >> 2) & 1; // n32 half
    const int wm   = wid >> 3;       // m16 half
    const int tokBase = blockIdx.x * TILE_M;

    const uint32_t aoff = (uint32_t)((wm * 16 + (lane & 15)) * RPITCH
                                     + (lane >> 4) * 16 + wk * 32);
    const uint32_t boff0 = (uint32_t)((wn2 * 32 + ((lane & 7) | ((lane >> 4) << 3))) * RPITCH
                                      + ((lane >> 3) & 1) * 16 + wk * 32);
    const uint32_t boff1 = boff0 + 16 * RPITCH;

    const int xr = tid >> 4;        // X staging row 0..31
    const int xs = tid & 15;        // 4-float segment

    float acc[4][4];                // [n8 tile: t*2+j][4]
#pragma unroll
    for (int i = 0; i < 4; i++)
#pragma unroll
        for (int j = 0; j < 4; j++) acc[i][j] = 0.f;
    float xq = 0.f;
    float4 rxA, rxB;                // X prefetch, 2 chunks deep

    auto ldgX = [&](float4& dst, int chunk) {
        const int k0 = chunk * KC;
        const float* xsrc = (k0 < D_HALF) ? t1 : t2;
        const int kx = k0 & (D_HALF - 1);
        dst = *(const float4*)(xsrc + (size_t)(tokBase + xr) * D_HALF + kx + xs * 4);
    };
    auto stsX = [&](int buf) {
        uint32_t h0 = pack_bf2(rxA.x, rxA.y);
        uint32_t h1 = pack_bf2(rxA.z, rxA.w);
        uint32_t l0 = pack_bf2(rxA.x - __uint_as_float(h0 << 16),
                               rxA.y - __uint_as_float(h0 & 0xffff0000u));
        uint32_t l1 = pack_bf2(rxA.z - __uint_as_float(h1 << 16),
                               rxA.w - __uint_as_float(h1 & 0xffff0000u));
        xq = fmaf(rxA.x, rxA.x, xq); xq = fmaf(rxA.y, rxA.y, xq);
        xq = fmaf(rxA.z, rxA.z, xq); xq = fmaf(rxA.w, rxA.w, xq);
        uint32_t xb = sb + (uint32_t)buf * XSTG_B + (uint32_t)(xr * RPITCH + xs * 8);
        sts64(xb + XH_OFF, h0, h1);
        sts64(xb + XL_OFF, l0, l1);
    };
    auto cpW = [&](int chunk) {
        const int k0 = chunk * KC;
        const uint32_t wb = sb + WBASE + (uint32_t)(chunk & (WSTAGES - 1)) * WSTG_B;
#pragma unroll
        for (int j = 0; j < 2; j++) {
            int i = tid + NTHR * j;           // 0..1023
            int half = i >> 9;                // 0: hi, 1: lo
            int r = (i >> 3) & 63;
            int c = i & 7;
            const uint32_t* srcb = half ? g_wl : g_wh;
            cp16(wb + (half ? WL_OFF : WH_OFF) + (uint32_t)(r * RPITCH + c * 16),
                 srcb + ((size_t)r * (KDIM / 2) + (k0 >> 1) + c * 4));
        }
        cp_commit();
    };

    // prologue
    ldgX(rxA, 0);
    ldgX(rxB, 1);
    cpW(0); cpW(1); cpW(2);

    for (int c = 0; c < NCHUNK; c++) {
        stsX(c & 1);
        rxA = rxB;
        if (c + 2 < NCHUNK) ldgX(rxB, c + 2);
        cp_wait<2>();                          // W_c landed
        __syncthreads();
        if (c + 3 < NCHUNK) cpW(c + 3);

        const uint32_t xb = sb + (uint32_t)(c & 1) * XSTG_B;
        const uint32_t wb = sb + WBASE + (uint32_t)(c & (WSTAGES - 1)) * WSTG_B;

        uint32_t ah[4], al[4], bh0[4], bh1[4], bl0[4], bl1[4];
        LDSM4(ah,  xb + XH_OFF + aoff);
        LDSM4(bh0, wb + WH_OFF + boff0);
        LDSM4(bh1, wb + WH_OFF + boff1);
        LDSM4(al,  xb + XL_OFF + aoff);
        LDSM4(bl0, wb + WL_OFF + boff0);
        LDSM4(bl1, wb + WL_OFF + boff1);

        MMA(acc[0], ah, bh0[0], bh0[1]);
        MMA(acc[1], ah, bh0[2], bh0[3]);
        MMA(acc[2], ah, bh1[0], bh1[1]);
        MMA(acc[3], ah, bh1[2], bh1[3]);
        MMA(acc[0], al, bh0[0], bh0[1]);
        MMA(acc[1], al, bh0[2], bh0[3]);
        MMA(acc[2], al, bh1[0], bh1[1]);
        MMA(acc[3], al, bh1[2], bh1[3]);
        MMA(acc[0], ah, bl0[0], bl0[1]);
        MMA(acc[1], ah, bl0[2], bl0[3]);
        MMA(acc[2], ah, bl1[0], bl1[1]);
        MMA(acc[3], ah, bl1[2], bl1[3]);
    }
    __syncthreads();                           // compute done before smem reuse

    // ---- epilogue: K-split partial dots -> smem, sum, top-2, scatter ----
    float* kd  = (float*)smem;                 // [4][32][DP]
    float* sxq = kd + 4 * TILE_M * DP;         // [32]

    {
        int r0 = wm * 16 + (lane >> 2);
        int cb = wn2 * 32 + (lane & 3) * 2;
#pragma unroll
        for (int t = 0; t < 2; t++)
#pragma unroll
            for (int j = 0; j < 2; j++) {
                const float* a = acc[t * 2 + j];
                int cc = cb + t * 16 + j * 8;
                kd[(wk * TILE_M + r0) * DP + cc]           = a[0];
                kd[(wk * TILE_M + r0) * DP + cc + 1]       = a[1];
                kd[(wk * TILE_M + r0 + 8) * DP + cc]       = a[2];
                kd[(wk * TILE_M + r0 + 8) * DP + cc + 1]   = a[3];
            }
    }
#pragma unroll
    for (int o = 8; o; o >>= 1) xq += __shfl_xor_sync(0xffffffffu, xq, o);
    if ((tid & 15) == 0) sxq[xr] = xq;
    __syncthreads();

    const float w0 = g_wsq[lane];
    const float w1 = g_wsq[lane + 32];
    const int e0 = lane, e1 = lane + 32;

#pragma unroll
    for (int tt = 0; tt < 2; tt++) {
        const int rloc = wid * 2 + tt;
        const int tok = tokBase + rloc;
        float d0 = (kd[(0 * TILE_M + rloc) * DP + e0] + kd[(1 * TILE_M + rloc) * DP + e0])
                 + (kd[(2 * TILE_M + rloc) * DP + e0] + kd[(3 * TILE_M + rloc) * DP + e0]);
        float d1 = (kd[(0 * TILE_M + rloc) * DP + e1] + kd[(1 * TILE_M + rloc) * DP + e1])
                 + (kd[(2 * TILE_M + rloc) * DP + e1] + kd[(3 * TILE_M + rloc) * DP + e1]);
        float p0 = fmaf(-2.f, d0, w0);
        float p1 = fmaf(-2.f, d1, w1);

        float v1, v2; int i1, i2;
        if (sless(p0, e0, p1, e1)) { v1 = p0; i1 = e0; v2 = p1; i2 = e1; }
        else                        { v1 = p1; i1 = e1; v2 = p0; i2 = e0; }
#pragma unroll
        for (int off = 16; off > 0; off >>= 1) {
            float u1 = __shfl_xor_sync(0xffffffffu, v1, off);
            int   j1 = __shfl_xor_sync(0xffffffffu, i1, off);
            float u2 = __shfl_xor_sync(0xffffffffu, v2, off);
            int   j2 = __shfl_xor_sync(0xffffffffu, i2, off);
            float n1, n2; int m1, m2;
            if (sless(u1, j1, v1, i1)) {
                n1 = u1; m1 = j1;
                if (sless(v1, i1, u2, j2)) { n2 = v1; m2 = i1; }
                else                        { n2 = u2; m2 = j2; }
            } else {
                n1 = v1; m1 = i1;
                if (sless(u1, j1, v2, i2)) { n2 = u1; m2 = j1; }
                else                        { n2 = v2; m2 = i2; }
            }
            v1 = n1; i1 = m1; v2 = n2; i2 = m2;
        }

        const float xqv = sxq[rloc];
        float s1 = xqv + v1; s1 = s1 > 0.f ? s1 : 0.f;
        float s2 = xqv + v2; s2 = s2 > 0.f ? s2 : 0.f;
        const float lg1 = -__fsqrt_rn(s1);
        const float lg2 = -__fsqrt_rn(s2);
        const float ed  = __expf(lg2 - lg1);
        const float inv = 1.f / (1.f + ed);
        const float ga  = inv;
        const float gb  = ed * inv;

        float o0 = (e0 == i1) ? ga : ((e0 == i2) ? gb : 0.f);
        float o1 = (e1 == i1) ? ga : ((e1 == i2) ? gb : 0.f);
        out[(size_t)tok * NEXP + e0] = o0;
        out[(size_t)tok * NEXP + e1] = o1;
    }
}

// ---------------------------------------------------------------------------
extern "C" void kernel_launch(void* const* d_in, const int* in_sizes, int n_in,
                              void* d_out, int out_size) {
    const float* t1 = (const float*)d_in[0];
    const float* t2 = (const float*)d_in[1];
    const float* w  = (const float*)d_in[2];
    float* out = (float*)d_out;

    cudaFuncSetAttribute(gemm_kernel,
                         cudaFuncAttributeMaxDynamicSharedMemorySize, SMEM_TOTAL);

    wsplit_kernel<<<NEXP, 256>>>(w);
    gemm_kernel<<<B_TOK / TILE_M, NTHR, SMEM_TOTAL>>>(t1, t2, out);
}